// round 5
// baseline (speedup 1.0000x reference)
#include <cuda_runtime.h>
#include <cstdint>
#include <cstddef>

#define NBOX 1024
#define NCLS 151
#define NC   150
#define MROW 4096
#define KDIM 4096
#define NREL 51
#define TH   0.3f

#define OUT_PREDS (NBOX * NCLS)        // 154624
#define OUT_REL   (OUT_PREDS + NBOX)   // 155648
#define NTASK 528                      // triangle (g,w) tiles per class

// ---------------- device scratch ----------------
__device__ float         g_probs[NBOX * NCLS];
__device__ unsigned char g_keep[NBOX * NC];            // [box][cls]

// ---------------- packed fp32x2 helpers ----------------
__device__ __forceinline__ unsigned long long pack2(float lo, float hi) {
    unsigned long long r;
    asm("mov.b64 %0, {%1, %2};" : "=l"(r) : "f"(lo), "f"(hi));
    return r;
}
__device__ __forceinline__ void fma2(unsigned long long& d, unsigned long long a,
                                     unsigned long long b) {
    asm("fma.rn.f32x2 %0, %1, %2, %0;" : "+l"(d) : "l"(a), "l"(b));
}
__device__ __forceinline__ void unpack2(unsigned long long v, float& lo, float& hi) {
    asm("mov.b64 {%0, %1}, %2;" : "=f"(lo), "=f"(hi) : "l"(v));
}

// ---------------- 1: softmax (warp per row) + logits passthrough ----------------
__global__ void k_softmax(const float* __restrict__ logits, float* __restrict__ out) {
    int warp = threadIdx.x >> 5, lane = threadIdx.x & 31;
    int row = blockIdx.x * 8 + warp;
    const float* rl = logits + row * NCLS;
    float v[5];
    float mx = -3.4e38f;
#pragma unroll
    for (int t = 0; t < 5; t++) {
        int c = lane + 32 * t;
        v[t] = (c < NCLS) ? rl[c] : -3.4e38f;
        mx = fmaxf(mx, v[t]);
    }
#pragma unroll
    for (int o = 16; o > 0; o >>= 1) mx = fmaxf(mx, __shfl_xor_sync(0xffffffffu, mx, o));
    float s = 0.f;
#pragma unroll
    for (int t = 0; t < 5; t++) {
        int c = lane + 32 * t;
        v[t] = (c < NCLS) ? expf(v[t] - mx) : 0.f;
        s += v[t];
    }
#pragma unroll
    for (int o = 16; o > 0; o >>= 1) s += __shfl_xor_sync(0xffffffffu, s, o);
#pragma unroll
    for (int t = 0; t < 5; t++) {
        int c = lane + 32 * t;
        if (c < NCLS) {
            g_probs[row * NCLS + c] = v[t] / s;
            out[row * NCLS + c]     = rl[c];
        }
    }
}

// ---------------- 2: init rel_dists region with bias ----------------
__global__ void k_initrel(const float* __restrict__ b, float* __restrict__ out) {
    int i = blockIdx.x * 256 + threadIdx.x;
    if (i < MROW * NREL) out[OUT_REL + i] = b[i % NREL];
}

// ---------------- 3: GEMM  rel = vr @ W.T + b  (f32x2, M-tile 256, 16-way ksplit)
__global__ __launch_bounds__(256) void k_gemm(const float* __restrict__ vr,
                                              const float* __restrict__ W,
                                              float* __restrict__ out) {
    extern __shared__ float smf[];
    float* As = smf;                                                // [256][33]
    unsigned long long* Wp = (unsigned long long*)(smf + 256 * 33); // [32][26]
    float* Wpf = (float*)Wp;

    int tid = threadIdx.x;
    int mg = tid >> 1, pg = tid & 1, pbase = pg * 13;
    int m0 = blockIdx.x * 256, k0 = blockIdx.y * 256;

    unsigned long long acc[2][13];
#pragma unroll
    for (int r = 0; r < 2; r++)
#pragma unroll
        for (int p = 0; p < 13; p++) acc[r][p] = 0ull;

    for (int kc = 0; kc < 256; kc += 32) {
#pragma unroll
        for (int u = 0; u < 8; u++) {
            int idx = u * 256 + tid;
            int row = idx >> 3, kq = idx & 7;
            float4 v = *(const float4*)&vr[(size_t)(m0 + row) * KDIM + (k0 + kc) + kq * 4];
            float* d = &As[row * 33 + kq * 4];
            d[0] = v.x; d[1] = v.y; d[2] = v.z; d[3] = v.w;
        }
        for (int u = tid; u < 52 * 32; u += 256) {
            int r = u >> 5, kk = u & 31;
            float val = (r < NREL) ? W[r * KDIM + (k0 + kc) + kk] : 0.f;
            Wpf[kk * 52 + r] = val;
        }
        __syncthreads();

        for (int kk = 0; kk < 32; kk++) {
            float a0 = As[(mg * 2 + 0) * 33 + kk];
            float a1 = As[(mg * 2 + 1) * 33 + kk];
            unsigned long long av0 = pack2(a0, a0), av1 = pack2(a1, a1);
#pragma unroll
            for (int p = 0; p < 13; p++) {
                unsigned long long wv = Wp[kk * 26 + pbase + p];
                fma2(acc[0][p], av0, wv);
                fma2(acc[1][p], av1, wv);
            }
        }
        __syncthreads();
    }

#pragma unroll
    for (int r = 0; r < 2; r++) {
        int row = m0 + mg * 2 + r;
#pragma unroll
        for (int p = 0; p < 13; p++) {
            float lo, hi;
            unpack2(acc[r][p], lo, hi);
            int rc = (pbase + p) * 2;
            atomicAdd(&out[OUT_REL + row * NREL + rc], lo);
            if (rc + 1 < NREL) atomicAdd(&out[OUT_REL + row * NREL + rc + 1], hi);
        }
    }
}

// ---------------- 4: FUSED per-class NMS: sort + iou-mask(smem) + scan -----------
// 150 CTAs x 1024 threads. smem: mask[1024][32] (keys alias) + boxes + ta + sidx.
__global__ __launch_bounds__(1024) void k_nms(const float4* __restrict__ boxes) {
    extern __shared__ unsigned smu[];
    unsigned* mask           = smu;                         // 32768 words (128KB)
    unsigned long long* keys = (unsigned long long*)smu;    // alias (sort phase only)
    float4* sb   = (float4*)(smu + 32768);                  // 16KB
    float*  ta   = (float*)(sb + NBOX);                     // 4KB
    int*    sidx = (int*)(ta + NBOX);                       // 4KB
    unsigned* keepw = (unsigned*)(sidx + NBOX);             // 128B

    int t = threadIdx.x;
    int cls = blockIdx.x + 1;                               // prob column
    int lane = t & 31, warpId = t >> 5;

    // ---- phase A: bitonic sort, 1 key/thread (descending, stable) ----
    float sc = g_probs[t * NCLS + cls];
    unsigned long long v = ((unsigned long long)__float_as_uint(sc) << 32) |
                           (unsigned)(0xFFFFFFFFu - (unsigned)t);
    for (int k = 2; k <= NBOX; k <<= 1) {
        for (int j = k >> 1; j >= 1; j >>= 1) {
            unsigned long long u;
            if (j >= 32) {
                __syncthreads();
                keys[t] = v;
                __syncthreads();
                u = keys[t ^ j];
            } else {
                u = __shfl_xor_sync(0xffffffffu, v, j);
            }
            bool takeMax = ((t & j) == 0) != ((t & k) != 0);
            v = takeMax ? (v > u ? v : u) : (v < u ? v : u);
        }
    }
    __syncthreads();    // sort done; keys region can be recycled as mask

    // ---- phase B: gather sorted boxes, areas; zero mask ----
    {
        int n = (int)(0xFFFFFFFFu - (unsigned)v);
        sidx[t] = n;
        float4 b4 = boxes[n * NCLS + cls];
        sb[t] = b4;
        ta[t] = TH * ((b4.z - b4.x) * (b4.w - b4.y));
#pragma unroll
        for (int w = 0; w < 8; w++)
            *(uint4*)&mask[(t << 5) | (w << 2)] = make_uint4(0, 0, 0, 0);
    }
    __syncthreads();

    // ---- phase C: suppression bitmask, true triangle, swizzled smem store ----
    for (int task = warpId; task < NTASK; task += 32) {
        // invert base(g) = 32g - g(g-1)/2
        int g = (int)((65.0f - sqrtf(4225.0f - 8.0f * (float)task)) * 0.5f);
        while (32 * (g + 1) - (((g + 1) * g) >> 1) <= task) g++;
        while (32 * g - ((g * (g - 1)) >> 1) > task) g--;
        int w = g + (task - (32 * g - ((g * (g - 1)) >> 1)));

        int r = (g << 5) | lane;
        float4 bi = sb[r];
        float c3i = ta[r] + TH * 1e-10f;
        int jbase = w << 5;
        unsigned bits = 0;
#pragma unroll 8
        for (int b = 0; b < 32; b++) {
            float4 bj = sb[jbase + b];                 // broadcast (warp-uniform)
            float rhs = c3i + ta[jbase + b];
            float ix1 = fmaxf(bi.x, bj.x);
            float iy1 = fmaxf(bi.y, bj.y);
            float ix2 = fminf(bi.z, bj.z);
            float iy2 = fminf(bi.w, bj.w);
            float iw = fmaxf(ix2 - ix1, 0.f);
            float ih = fmaxf(iy2 - iy1, 0.f);
            float inter = iw * ih;
            if (fmaf(TH, inter, inter) > rhs) bits |= (1u << b);
        }
        if (w == g) bits &= (0xFFFFFFFEu << lane);     // only j > row in diag word
        mask[(r << 5) | (w ^ lane)] = bits;            // swizzle: conflict-free
    }
    __syncthreads();

    // ---- phase D: greedy scan (warp 0), register-resolve + batched OR ----
    if (t < 32) {
        int l = t;
        unsigned rem = 0;                              // lane l owns word l
        for (int wb = 0; wb < 32; wb++) {
            unsigned diag[32];
#pragma unroll
            for (int b = 0; b < 32; b++)
                diag[b] = mask[((((wb << 5) | b)) << 5) | (wb ^ b)];   // broadcast
            unsigned alive = ~__shfl_sync(0xffffffffu, rem, wb);
            unsigned K = 0;
#pragma unroll
            for (int b = 0; b < 32; b++) {             // branchless greedy in regs
                unsigned m = (unsigned)(-(int)((alive >> b) & 1u));
                K |= (1u << b) & m;
                alive &= ~(diag[b] & m);
            }
            if (l == 0) keepw[wb] = K;                 // K lane-uniform
            unsigned kk = K;                           // OR kept rows (CF via swizzle)
            while (kk) {
                int b = __ffs(kk) - 1; kk &= kk - 1;
                rem |= mask[((((wb << 5) | b)) << 5) | (l ^ b)];
            }
        }
    }
    __syncthreads();

    // ---- phase E: scatter keep flags ----
    {
        unsigned kept = (keepw[t >> 5] >> (t & 31)) & 1u;
        int n = sidx[t];
        g_keep[n * NC + (cls - 1)] = (unsigned char)kept;
    }
}

// ---------------- 5: masked argmax -> obj_preds ----------------
__global__ void k_argmax(float* __restrict__ out) {
    int n = blockIdx.x * 256 + threadIdx.x;
    if (n >= NBOX) return;
    float best = -1.f;
    int bestc = 0;
    for (int c = 1; c < NCLS; c++) {
        float v = g_keep[n * NC + (c - 1)] ? g_probs[n * NCLS + c] : 0.f;
        if (v > best) { best = v; bestc = c; }
    }
    out[OUT_PREDS + n] = (float)bestc;
}

// ---------------- launch ----------------
extern "C" void kernel_launch(void* const* d_in, const int* in_sizes, int n_in,
                              void* d_out, int out_size) {
    const float*  logits = (const float*)d_in[0];
    const float*  vr     = (const float*)d_in[1];
    const float4* boxes  = (const float4*)d_in[2];
    const float*  W      = (const float*)d_in[3];
    const float*  b      = (const float*)d_in[4];
    float* out = (float*)d_out;

    static cudaStream_t s2 = nullptr;
    static cudaEvent_t  evA = nullptr, evB = nullptr;
    if (!s2) {
        cudaStreamCreateWithFlags(&s2, cudaStreamNonBlocking);
        cudaEventCreateWithFlags(&evA, cudaEventDisableTiming);
        cudaEventCreateWithFlags(&evB, cudaEventDisableTiming);
    }

    const int nms_smem  = 32768 * 4 + NBOX * 16 + NBOX * 4 + NBOX * 4 + 128; // 155776
    const int gemm_smem = 256 * 33 * 4 + 32 * 26 * 8;                        // 40448
    cudaFuncSetAttribute(k_nms,  cudaFuncAttributeMaxDynamicSharedMemorySize, nms_smem);
    cudaFuncSetAttribute(k_gemm, cudaFuncAttributeMaxDynamicSharedMemorySize, gemm_smem);

    // fork: GEMM branch independent of NMS chain (can co-reside on SMs)
    cudaEventRecord(evA, 0);
    cudaStreamWaitEvent(s2, evA, 0);
    k_initrel<<<(MROW * NREL + 255) / 256, 256, 0, s2>>>(b, out);
    k_gemm<<<dim3(16, 16), 256, gemm_smem, s2>>>(vr, W, out);
    cudaEventRecord(evB, s2);

    // NMS chain
    k_softmax<<<128, 256>>>(logits, out);
    k_nms<<<NC, 1024, nms_smem>>>(boxes);
    k_argmax<<<4, 256>>>(out);

    cudaStreamWaitEvent(0, evB, 0);
}

// round 7
// speedup vs baseline: 1.1677x; 1.1677x over previous
#include <cuda_runtime.h>
#include <cstdint>
#include <cstddef>

#define NBOX 1024
#define NCLS 151
#define NC   150
#define MROW 4096
#define KDIM 4096
#define NREL 51
#define TH   0.3f

#define OUT_PREDS (NBOX * NCLS)        // 154624
#define OUT_REL   (OUT_PREDS + NBOX)   // 155648
#define NTASK 528                      // triangle (g,w) tiles per class
#define TRI   16928                    // padded triangle words per class

// colbase[w] = 16*w*(w+1) + w  (32*(w+1) rows per word w, +1 pad word for banks)
__device__ __forceinline__ int colbase(int w) { return 16 * w * (w + 1) + w; }

// ---------------- device scratch ----------------
__device__ float         g_probs[NBOX * NCLS];
__device__ float4        g_sboxes[NC * NBOX];
__device__ int           g_sidx[NC * NBOX];
__device__ unsigned      g_masktri[NC * TRI];          // 10.2 MB, triangle-packed
__device__ unsigned char g_keep[NBOX * NC];            // [box][cls]

// ---------------- packed fp32x2 helpers ----------------
__device__ __forceinline__ unsigned long long pack2(float lo, float hi) {
    unsigned long long r;
    asm("mov.b64 %0, {%1, %2};" : "=l"(r) : "f"(lo), "f"(hi));
    return r;
}
__device__ __forceinline__ void fma2(unsigned long long& d, unsigned long long a,
                                     unsigned long long b) {
    asm("fma.rn.f32x2 %0, %1, %2, %0;" : "+l"(d) : "l"(a), "l"(b));
}
__device__ __forceinline__ void unpack2(unsigned long long v, float& lo, float& hi) {
    asm("mov.b64 {%0, %1}, %2;" : "=f"(lo), "=f"(hi) : "l"(v));
}

// ---------------- 1: softmax (warp per row) + logits passthrough ----------------
__global__ void k_softmax(const float* __restrict__ logits, float* __restrict__ out) {
    int warp = threadIdx.x >> 5, lane = threadIdx.x & 31;
    int row = blockIdx.x * 8 + warp;
    const float* rl = logits + row * NCLS;
    float v[5];
    float mx = -3.4e38f;
#pragma unroll
    for (int t = 0; t < 5; t++) {
        int c = lane + 32 * t;
        v[t] = (c < NCLS) ? rl[c] : -3.4e38f;
        mx = fmaxf(mx, v[t]);
    }
#pragma unroll
    for (int o = 16; o > 0; o >>= 1) mx = fmaxf(mx, __shfl_xor_sync(0xffffffffu, mx, o));
    float s = 0.f;
#pragma unroll
    for (int t = 0; t < 5; t++) {
        int c = lane + 32 * t;
        v[t] = (c < NCLS) ? expf(v[t] - mx) : 0.f;
        s += v[t];
    }
#pragma unroll
    for (int o = 16; o > 0; o >>= 1) s += __shfl_xor_sync(0xffffffffu, s, o);
#pragma unroll
    for (int t = 0; t < 5; t++) {
        int c = lane + 32 * t;
        if (c < NCLS) {
            g_probs[row * NCLS + c] = v[t] / s;
            out[row * NCLS + c]     = rl[c];
        }
    }
}

// ---------------- 2: init rel_dists region with bias ----------------
__global__ void k_initrel(const float* __restrict__ b, float* __restrict__ out) {
    int i = blockIdx.x * 256 + threadIdx.x;
    if (i < MROW * NREL) out[OUT_REL + i] = b[i % NREL];
}

// ---------------- 3: GEMM  rel = vr @ W.T + b  (f32x2, M-tile 256, 16-way ksplit)
__global__ __launch_bounds__(256) void k_gemm(const float* __restrict__ vr,
                                              const float* __restrict__ W,
                                              float* __restrict__ out) {
    extern __shared__ float smf[];
    float* As = smf;                                                // [256][33]
    unsigned long long* Wp = (unsigned long long*)(smf + 256 * 33); // [32][26]
    float* Wpf = (float*)Wp;

    int tid = threadIdx.x;
    int mg = tid >> 1, pg = tid & 1, pbase = pg * 13;
    int m0 = blockIdx.x * 256, k0 = blockIdx.y * 256;

    unsigned long long acc[2][13];
#pragma unroll
    for (int r = 0; r < 2; r++)
#pragma unroll
        for (int p = 0; p < 13; p++) acc[r][p] = 0ull;

    for (int kc = 0; kc < 256; kc += 32) {
#pragma unroll
        for (int u = 0; u < 8; u++) {
            int idx = u * 256 + tid;
            int row = idx >> 3, kq = idx & 7;
            float4 v = *(const float4*)&vr[(size_t)(m0 + row) * KDIM + (k0 + kc) + kq * 4];
            float* d = &As[row * 33 + kq * 4];
            d[0] = v.x; d[1] = v.y; d[2] = v.z; d[3] = v.w;
        }
        for (int u = tid; u < 52 * 32; u += 256) {
            int r = u >> 5, kk = u & 31;
            float val = (r < NREL) ? W[r * KDIM + (k0 + kc) + kk] : 0.f;
            Wpf[kk * 52 + r] = val;
        }
        __syncthreads();

        for (int kk = 0; kk < 32; kk++) {
            float a0 = As[(mg * 2 + 0) * 33 + kk];
            float a1 = As[(mg * 2 + 1) * 33 + kk];
            unsigned long long av0 = pack2(a0, a0), av1 = pack2(a1, a1);
#pragma unroll
            for (int p = 0; p < 13; p++) {
                unsigned long long wv = Wp[kk * 26 + pbase + p];
                fma2(acc[0][p], av0, wv);
                fma2(acc[1][p], av1, wv);
            }
        }
        __syncthreads();
    }

#pragma unroll
    for (int r = 0; r < 2; r++) {
        int row = m0 + mg * 2 + r;
#pragma unroll
        for (int p = 0; p < 13; p++) {
            float lo, hi;
            unpack2(acc[r][p], lo, hi);
            int rc = (pbase + p) * 2;
            atomicAdd(&out[OUT_REL + row * NREL + rc], lo);
            if (rc + 1 < NREL) atomicAdd(&out[OUT_REL + row * NREL + rc + 1], hi);
        }
    }
}

// ---------------- 4: per-class descending sort (register/shfl bitonic) -----------
__global__ __launch_bounds__(512) void k_sort(const float4* __restrict__ boxes) {
    __shared__ unsigned long long keys[NBOX];
    int t = threadIdx.x;
    int cls = blockIdx.x + 1;

    auto mkkey = [&](int p) {
        float sc = g_probs[p * NCLS + cls];
        return ((unsigned long long)__float_as_uint(sc) << 32) |
               (unsigned)(0xFFFFFFFFu - (unsigned)p);
    };
    unsigned long long v0 = mkkey(2 * t), v1 = mkkey(2 * t + 1);

    for (int k = 2; k <= NBOX; k <<= 1) {
        for (int j = k >> 1; j >= 1; j >>= 1) {
            if (j >= 64) {
                __syncthreads();
                keys[2 * t] = v0; keys[2 * t + 1] = v1;
                __syncthreads();
                unsigned long long u0 = keys[(2 * t) ^ j];
                unsigned long long u1 = keys[((2 * t) ^ j) + 1];
                bool takeMax = (((t & (j >> 1)) == 0) == ((t & (k >> 1)) == 0));
                v0 = takeMax ? (v0 > u0 ? v0 : u0) : (v0 < u0 ? v0 : u0);
                v1 = takeMax ? (v1 > u1 ? v1 : u1) : (v1 < u1 ? v1 : u1);
            } else if (j >= 2) {
                unsigned long long u0 = __shfl_xor_sync(0xffffffffu, v0, j >> 1);
                unsigned long long u1 = __shfl_xor_sync(0xffffffffu, v1, j >> 1);
                bool takeMax = (((t & (j >> 1)) == 0) == ((t & (k >> 1)) == 0));
                v0 = takeMax ? (v0 > u0 ? v0 : u0) : (v0 < u0 ? v0 : u0);
                v1 = takeMax ? (v1 > u1 ? v1 : u1) : (v1 < u1 ? v1 : u1);
            } else {
                bool desc = ((t & (k >> 1)) == 0);
                unsigned long long hi = v0 > v1 ? v0 : v1;
                unsigned long long lo = v0 > v1 ? v1 : v0;
                v0 = desc ? hi : lo;
                v1 = desc ? lo : hi;
            }
        }
    }
    int n0 = (int)(0xFFFFFFFFu - (unsigned)v0);
    int n1 = (int)(0xFFFFFFFFu - (unsigned)v1);
    g_sidx[(cls - 1) * NBOX + 2 * t]     = n0;
    g_sidx[(cls - 1) * NBOX + 2 * t + 1] = n1;
    g_sboxes[(cls - 1) * NBOX + 2 * t]     = boxes[n0 * NCLS + cls];
    g_sboxes[(cls - 1) * NBOX + 2 * t + 1] = boxes[n1 * NCLS + cls];
}

// ---------------- 5: suppression bitmask -> triangle-packed gmem -----------------
// warp = (row-group g, word w), w>=g; lane = row; bj broadcast; store stride-1.
__global__ __launch_bounds__(1024) void k_iou() {
    __shared__ float4 sb[NBOX];
    __shared__ float  ta[NBOX];
    int tid = threadIdx.x, cls = blockIdx.y;
    {
        float4 b4 = g_sboxes[cls * NBOX + tid];
        sb[tid] = b4;
        ta[tid] = TH * ((b4.z - b4.x) * (b4.w - b4.y));
    }
    __syncthreads();
    int task = blockIdx.x * 32 + (tid >> 5);
    if (task >= NTASK) return;

    // invert base(g) = 32g - g(g-1)/2
    int g = (int)((65.0f - sqrtf(4225.0f - 8.0f * (float)task)) * 0.5f);
    while (32 * (g + 1) - (((g + 1) * g) >> 1) <= task) g++;
    while (32 * g - ((g * (g - 1)) >> 1) > task) g--;
    int w = g + (task - (32 * g - ((g * (g - 1)) >> 1)));

    int lane = tid & 31;
    int r = (g << 5) | lane;
    float4 bi = sb[r];
    float c3i = ta[r] + TH * 1e-10f;
    int jbase = w << 5;
    unsigned bits = 0;
#pragma unroll 8
    for (int b = 0; b < 32; b++) {
        float4 bj = sb[jbase + b];                 // broadcast (warp-uniform)
        float rhs = c3i + ta[jbase + b];
        float ix1 = fmaxf(bi.x, bj.x);
        float iy1 = fmaxf(bi.y, bj.y);
        float ix2 = fminf(bi.z, bj.z);
        float iy2 = fminf(bi.w, bj.w);
        float iw = fmaxf(ix2 - ix1, 0.f);
        float ih = fmaxf(iy2 - iy1, 0.f);
        float inter = iw * ih;
        if (fmaf(TH, inter, inter) > rhs) bits |= (1u << b);
    }
    if (w == g) bits &= (0xFFFFFFFEu << lane);     // only j > row in diag word
    g_masktri[cls * TRI + colbase(w) + r] = bits;  // coalesced 128B line
}

// ---------------- 6: greedy scan on triangle mask (single wave now) --------------
__global__ __launch_bounds__(512) void k_scan() {
    extern __shared__ unsigned sm[];   // tri[TRI] + keepw[32]
    unsigned* tri = sm;
    unsigned* keepw = sm + TRI;
    int tid = threadIdx.x, cls = blockIdx.x;
    const uint4* src = (const uint4*)(g_masktri + (size_t)cls * TRI);
    uint4* dst = (uint4*)tri;
    for (int t = tid; t < TRI / 4; t += 512) dst[t] = src[t];
    __syncthreads();

    if (tid < 32) {
        int l = tid;
        int cbl = colbase(l);                      // per-lane column base
        unsigned rem = 0;                          // lane l owns word l
        for (int wb = 0; wb < 32; wb++) {
            int cbw = colbase(wb) + (wb << 5);
            unsigned diag[32];
#pragma unroll
            for (int b = 0; b < 32; b++) diag[b] = tri[cbw + b];   // broadcast
            unsigned alive = ~__shfl_sync(0xffffffffu, rem, wb);
            unsigned K = 0;
#pragma unroll
            for (int b = 0; b < 32; b++) {         // branchless greedy in regs
                unsigned m = (unsigned)(-(int)((alive >> b) & 1u));
                K |= (1u << b) & m;
                alive &= ~(diag[b] & m);
            }
            if (l == 0) keepw[wb] = K;             // K lane-uniform
            unsigned kk = K;                       // OR kept rows; banks (l+R)%32: CF
            while (kk) {
                int b = __ffs(kk) - 1; kk &= kk - 1;
                int R = (wb << 5) | b;
                if (l >= wb) rem |= tri[cbl + R];  // word l exists iff l >= q_R(=wb)
            }
        }
    }
    __syncthreads();
    for (int p = tid; p < NBOX; p += 512) {
        unsigned kept = (keepw[p >> 5] >> (p & 31)) & 1u;
        int n = g_sidx[cls * NBOX + p];
        g_keep[n * NC + cls] = (unsigned char)kept;
    }
}

// ---------------- 7: masked argmax -> obj_preds ----------------
__global__ void k_argmax(float* __restrict__ out) {
    int n = blockIdx.x * 256 + threadIdx.x;
    if (n >= NBOX) return;
    float best = -1.f;
    int bestc = 0;
    for (int c = 1; c < NCLS; c++) {
        float v = g_keep[n * NC + (c - 1)] ? g_probs[n * NCLS + c] : 0.f;
        if (v > best) { best = v; bestc = c; }
    }
    out[OUT_PREDS + n] = (float)bestc;
}

// ---------------- launch ----------------
extern "C" void kernel_launch(void* const* d_in, const int* in_sizes, int n_in,
                              void* d_out, int out_size) {
    const float*  logits = (const float*)d_in[0];
    const float*  vr     = (const float*)d_in[1];
    const float4* boxes  = (const float4*)d_in[2];
    const float*  W      = (const float*)d_in[3];
    const float*  b      = (const float*)d_in[4];
    float* out = (float*)d_out;

    static cudaStream_t s2 = nullptr;
    static cudaEvent_t  evA = nullptr, evB = nullptr;
    if (!s2) {
        cudaStreamCreateWithFlags(&s2, cudaStreamNonBlocking);
        cudaEventCreateWithFlags(&evA, cudaEventDisableTiming);
        cudaEventCreateWithFlags(&evB, cudaEventDisableTiming);
    }

    const int scan_smem = (TRI + 32) * 4;                // 67840
    const int gemm_smem = 256 * 33 * 4 + 32 * 26 * 8;    // 40448
    cudaFuncSetAttribute(k_scan, cudaFuncAttributeMaxDynamicSharedMemorySize, scan_smem);
    cudaFuncSetAttribute(k_gemm, cudaFuncAttributeMaxDynamicSharedMemorySize, gemm_smem);

    // fork point recorded first: GEMM branch is a graph root (runs from t=0)
    cudaEventRecord(evA, 0);
    cudaStreamWaitEvent(s2, evA, 0);

    k_softmax<<<128, 256>>>(logits, out);                          // launch 1
    k_sort<<<NC, 512>>>(boxes);                                    // launch 2
    k_iou<<<dim3(17, NC), 1024>>>();                               // launch 3
    k_scan<<<NC, 512, scan_smem>>>();                              // launch 4 (profiled)
    k_initrel<<<(MROW * NREL + 255) / 256, 256, 0, s2>>>(b, out);  // launch 5
    k_gemm<<<dim3(16, 16), 256, gemm_smem, s2>>>(vr, W, out);      // launch 6
    k_argmax<<<4, 256>>>(out);                                     // launch 7

    cudaEventRecord(evB, s2);
    cudaStreamWaitEvent(0, evB, 0);
}

// round 8
// speedup vs baseline: 1.3070x; 1.1193x over previous
#include <cuda_runtime.h>
#include <cstdint>
#include <cstddef>

#define NBOX 1024
#define NCLS 151
#define NC   150
#define MROW 4096
#define KDIM 4096
#define NREL 51
#define TH   0.3f

#define OUT_PREDS (NBOX * NCLS)        // 154624
#define OUT_REL   (OUT_PREDS + NBOX)   // 155648
#define NTASK 528                      // triangle (g,w) tiles per class
#define TRI   16928                    // padded triangle words per class

// colbase[w] = 16*w*(w+1) + w  (32*(w+1) rows per word w, +1 pad word for banks)
__device__ __forceinline__ int colbase(int w) { return 16 * w * (w + 1) + w; }

// ---------------- device scratch ----------------
__device__ float         g_probs[NBOX * NCLS];
__device__ float4        g_sboxes[NC * NBOX];
__device__ int           g_sidx[NC * NBOX];
__device__ unsigned      g_masktri[NC * TRI];          // 10.2 MB, triangle-packed
__device__ unsigned char g_keep[NBOX * NC];            // [box][cls]

// ---------------- packed fp32x2 helpers ----------------
__device__ __forceinline__ unsigned long long pack2(float lo, float hi) {
    unsigned long long r;
    asm("mov.b64 %0, {%1, %2};" : "=l"(r) : "f"(lo), "f"(hi));
    return r;
}
__device__ __forceinline__ void fma2(unsigned long long& d, unsigned long long a,
                                     unsigned long long b) {
    asm("fma.rn.f32x2 %0, %1, %2, %0;" : "+l"(d) : "l"(a), "l"(b));
}
__device__ __forceinline__ void unpack2(unsigned long long v, float& lo, float& hi) {
    asm("mov.b64 {%0, %1}, %2;" : "=f"(lo), "=f"(hi) : "l"(v));
}

// ---------------- 1: softmax (warp per row) + logits passthrough ----------------
__global__ void k_softmax(const float* __restrict__ logits, float* __restrict__ out) {
    int warp = threadIdx.x >> 5, lane = threadIdx.x & 31;
    int row = blockIdx.x * 8 + warp;
    const float* rl = logits + row * NCLS;
    float v[5];
    float mx = -3.4e38f;
#pragma unroll
    for (int t = 0; t < 5; t++) {
        int c = lane + 32 * t;
        v[t] = (c < NCLS) ? rl[c] : -3.4e38f;
        mx = fmaxf(mx, v[t]);
    }
#pragma unroll
    for (int o = 16; o > 0; o >>= 1) mx = fmaxf(mx, __shfl_xor_sync(0xffffffffu, mx, o));
    float s = 0.f;
#pragma unroll
    for (int t = 0; t < 5; t++) {
        int c = lane + 32 * t;
        v[t] = (c < NCLS) ? expf(v[t] - mx) : 0.f;
        s += v[t];
    }
#pragma unroll
    for (int o = 16; o > 0; o >>= 1) s += __shfl_xor_sync(0xffffffffu, s, o);
#pragma unroll
    for (int t = 0; t < 5; t++) {
        int c = lane + 32 * t;
        if (c < NCLS) {
            g_probs[row * NCLS + c] = v[t] / s;
            out[row * NCLS + c]     = rl[c];
        }
    }
}

// ---------------- 2: init rel_dists region with bias ----------------
__global__ void k_initrel(const float* __restrict__ b, float* __restrict__ out) {
    int i = blockIdx.x * 256 + threadIdx.x;
    if (i < MROW * NREL) out[OUT_REL + i] = b[i % NREL];
}

// ---------------- 3: GEMM  rel = vr @ W.T + b  (f32x2, M-tile 256, 16-way ksplit)
__global__ __launch_bounds__(256) void k_gemm(const float* __restrict__ vr,
                                              const float* __restrict__ W,
                                              float* __restrict__ out) {
    extern __shared__ float smf[];
    float* As = smf;                                                // [256][33]
    unsigned long long* Wp = (unsigned long long*)(smf + 256 * 33); // [32][26]
    float* Wpf = (float*)Wp;

    int tid = threadIdx.x;
    int mg = tid >> 1, pg = tid & 1, pbase = pg * 13;
    int m0 = blockIdx.x * 256, k0 = blockIdx.y * 256;

    unsigned long long acc[2][13];
#pragma unroll
    for (int r = 0; r < 2; r++)
#pragma unroll
        for (int p = 0; p < 13; p++) acc[r][p] = 0ull;

    for (int kc = 0; kc < 256; kc += 32) {
#pragma unroll
        for (int u = 0; u < 8; u++) {
            int idx = u * 256 + tid;
            int row = idx >> 3, kq = idx & 7;
            float4 v = *(const float4*)&vr[(size_t)(m0 + row) * KDIM + (k0 + kc) + kq * 4];
            float* d = &As[row * 33 + kq * 4];
            d[0] = v.x; d[1] = v.y; d[2] = v.z; d[3] = v.w;
        }
        for (int u = tid; u < 52 * 32; u += 256) {
            int r = u >> 5, kk = u & 31;
            float val = (r < NREL) ? W[r * KDIM + (k0 + kc) + kk] : 0.f;
            Wpf[kk * 52 + r] = val;
        }
        __syncthreads();

        for (int kk = 0; kk < 32; kk++) {
            float a0 = As[(mg * 2 + 0) * 33 + kk];
            float a1 = As[(mg * 2 + 1) * 33 + kk];
            unsigned long long av0 = pack2(a0, a0), av1 = pack2(a1, a1);
#pragma unroll
            for (int p = 0; p < 13; p++) {
                unsigned long long wv = Wp[kk * 26 + pbase + p];
                fma2(acc[0][p], av0, wv);
                fma2(acc[1][p], av1, wv);
            }
        }
        __syncthreads();
    }

#pragma unroll
    for (int r = 0; r < 2; r++) {
        int row = m0 + mg * 2 + r;
#pragma unroll
        for (int p = 0; p < 13; p++) {
            float lo, hi;
            unpack2(acc[r][p], lo, hi);
            int rc = (pbase + p) * 2;
            atomicAdd(&out[OUT_REL + row * NREL + rc], lo);
            if (rc + 1 < NREL) atomicAdd(&out[OUT_REL + row * NREL + rc + 1], hi);
        }
    }
}

// ---------------- 4: per-class descending sort (register/shfl bitonic) -----------
__global__ __launch_bounds__(512) void k_sort(const float4* __restrict__ boxes) {
    __shared__ unsigned long long keys[NBOX];
    int t = threadIdx.x;
    int cls = blockIdx.x + 1;

    auto mkkey = [&](int p) {
        float sc = g_probs[p * NCLS + cls];
        return ((unsigned long long)__float_as_uint(sc) << 32) |
               (unsigned)(0xFFFFFFFFu - (unsigned)p);
    };
    unsigned long long v0 = mkkey(2 * t), v1 = mkkey(2 * t + 1);

    for (int k = 2; k <= NBOX; k <<= 1) {
        for (int j = k >> 1; j >= 1; j >>= 1) {
            if (j >= 64) {
                __syncthreads();
                keys[2 * t] = v0; keys[2 * t + 1] = v1;
                __syncthreads();
                unsigned long long u0 = keys[(2 * t) ^ j];
                unsigned long long u1 = keys[((2 * t) ^ j) + 1];
                bool takeMax = (((t & (j >> 1)) == 0) == ((t & (k >> 1)) == 0));
                v0 = takeMax ? (v0 > u0 ? v0 : u0) : (v0 < u0 ? v0 : u0);
                v1 = takeMax ? (v1 > u1 ? v1 : u1) : (v1 < u1 ? v1 : u1);
            } else if (j >= 2) {
                unsigned long long u0 = __shfl_xor_sync(0xffffffffu, v0, j >> 1);
                unsigned long long u1 = __shfl_xor_sync(0xffffffffu, v1, j >> 1);
                bool takeMax = (((t & (j >> 1)) == 0) == ((t & (k >> 1)) == 0));
                v0 = takeMax ? (v0 > u0 ? v0 : u0) : (v0 < u0 ? v0 : u0);
                v1 = takeMax ? (v1 > u1 ? v1 : u1) : (v1 < u1 ? v1 : u1);
            } else {
                bool desc = ((t & (k >> 1)) == 0);
                unsigned long long hi = v0 > v1 ? v0 : v1;
                unsigned long long lo = v0 > v1 ? v1 : v0;
                v0 = desc ? hi : lo;
                v1 = desc ? lo : hi;
            }
        }
    }
    int n0 = (int)(0xFFFFFFFFu - (unsigned)v0);
    int n1 = (int)(0xFFFFFFFFu - (unsigned)v1);
    g_sidx[(cls - 1) * NBOX + 2 * t]     = n0;
    g_sidx[(cls - 1) * NBOX + 2 * t + 1] = n1;
    g_sboxes[(cls - 1) * NBOX + 2 * t]     = boxes[n0 * NCLS + cls];
    g_sboxes[(cls - 1) * NBOX + 2 * t + 1] = boxes[n1 * NCLS + cls];
}

// ---------------- 5: suppression bitmask -> triangle-packed gmem -----------------
__global__ __launch_bounds__(1024) void k_iou() {
    __shared__ float4 sb[NBOX];
    __shared__ float  ta[NBOX];
    int tid = threadIdx.x, cls = blockIdx.y;
    {
        float4 b4 = g_sboxes[cls * NBOX + tid];
        sb[tid] = b4;
        ta[tid] = TH * ((b4.z - b4.x) * (b4.w - b4.y));
    }
    __syncthreads();
    int task = blockIdx.x * 32 + (tid >> 5);
    if (task >= NTASK) return;

    // invert base(g) = 32g - g(g-1)/2
    int g = (int)((65.0f - sqrtf(4225.0f - 8.0f * (float)task)) * 0.5f);
    while (32 * (g + 1) - (((g + 1) * g) >> 1) <= task) g++;
    while (32 * g - ((g * (g - 1)) >> 1) > task) g--;
    int w = g + (task - (32 * g - ((g * (g - 1)) >> 1)));

    int lane = tid & 31;
    int r = (g << 5) | lane;
    float4 bi = sb[r];
    float c3i = ta[r] + TH * 1e-10f;
    int jbase = w << 5;
    unsigned bits = 0;
#pragma unroll 8
    for (int b = 0; b < 32; b++) {
        float4 bj = sb[jbase + b];                 // broadcast (warp-uniform)
        float rhs = c3i + ta[jbase + b];
        float ix1 = fmaxf(bi.x, bj.x);
        float iy1 = fmaxf(bi.y, bj.y);
        float ix2 = fminf(bi.z, bj.z);
        float iy2 = fminf(bi.w, bj.w);
        float iw = fmaxf(ix2 - ix1, 0.f);
        float ih = fmaxf(iy2 - iy1, 0.f);
        float inter = iw * ih;
        if (fmaf(TH, inter, inter) > rhs) bits |= (1u << b);
    }
    if (w == g) bits &= (0xFFFFFFFEu << lane);     // only j > row in diag word
    g_masktri[cls * TRI + colbase(w) + r] = bits;  // coalesced 128B line
}

// ---------------- 6: greedy scan: diag pinned in regs, 12-cyc greedy steps -------
__global__ __launch_bounds__(512, 1) void k_scan() {
    extern __shared__ unsigned sm[];   // tri[TRI] + keepw[32]
    unsigned* tri = sm;
    unsigned* keepw = sm + TRI;
    int tid = threadIdx.x, cls = blockIdx.x;
    const uint4* src = (const uint4*)(g_masktri + (size_t)cls * TRI);
    uint4* dst = (uint4*)tri;
    for (int t = tid; t < TRI / 4; t += 512) dst[t] = src[t];
    __syncthreads();

    if (tid < 32) {
        int l = tid;
        int cbl = colbase(l);
        unsigned rem = 0;                          // lane l owns word l
        volatile unsigned* vtri = tri;             // pin loads: issue early, keep in regs
        for (int wb = 0; wb < 32; wb++) {
            int cbw = colbase(wb) + (wb << 5);
            // 32 named regs, volatile loads issued up-front (latencies overlap)
            unsigned d0 = vtri[cbw+0],  d1 = vtri[cbw+1],  d2 = vtri[cbw+2],  d3 = vtri[cbw+3];
            unsigned d4 = vtri[cbw+4],  d5 = vtri[cbw+5],  d6 = vtri[cbw+6],  d7 = vtri[cbw+7];
            unsigned d8 = vtri[cbw+8],  d9 = vtri[cbw+9],  d10= vtri[cbw+10], d11= vtri[cbw+11];
            unsigned d12= vtri[cbw+12], d13= vtri[cbw+13], d14= vtri[cbw+14], d15= vtri[cbw+15];
            unsigned d16= vtri[cbw+16], d17= vtri[cbw+17], d18= vtri[cbw+18], d19= vtri[cbw+19];
            unsigned d20= vtri[cbw+20], d21= vtri[cbw+21], d22= vtri[cbw+22], d23= vtri[cbw+23];
            unsigned d24= vtri[cbw+24], d25= vtri[cbw+25], d26= vtri[cbw+26], d27= vtri[cbw+27];
            unsigned d28= vtri[cbw+28], d29= vtri[cbw+29], d30= vtri[cbw+30], d31= vtri[cbw+31];

            unsigned alive = ~__shfl_sync(0xffffffffu, rem, wb);
            unsigned K = 0;
            // chain per step: SHF, SHF, LOP3 (~12 cyc); K-update off the chain
#define GSTEP(B, D) { unsigned m = (unsigned)(((int)(alive << (31 - B))) >> 31); \
                      K |= m & (1u << B); alive &= ~((D) & m); }
            GSTEP(0,d0)  GSTEP(1,d1)  GSTEP(2,d2)  GSTEP(3,d3)
            GSTEP(4,d4)  GSTEP(5,d5)  GSTEP(6,d6)  GSTEP(7,d7)
            GSTEP(8,d8)  GSTEP(9,d9)  GSTEP(10,d10) GSTEP(11,d11)
            GSTEP(12,d12) GSTEP(13,d13) GSTEP(14,d14) GSTEP(15,d15)
            GSTEP(16,d16) GSTEP(17,d17) GSTEP(18,d18) GSTEP(19,d19)
            GSTEP(20,d20) GSTEP(21,d21) GSTEP(22,d22) GSTEP(23,d23)
            GSTEP(24,d24) GSTEP(25,d25) GSTEP(26,d26) GSTEP(27,d27)
            GSTEP(28,d28) GSTEP(29,d29) GSTEP(30,d30) GSTEP(31,d31)
#undef GSTEP
            if (l == 0) keepw[wb] = K;             // K lane-uniform
            unsigned kk = K;                       // OR kept rows; banks (l+R)%32: CF
            while (kk) {
                int b = __ffs(kk) - 1; kk &= kk - 1;
                int R = (wb << 5) | b;
                if (l >= wb) rem |= tri[cbl + R];  // word l exists iff l >= wb
            }
        }
    }
    __syncthreads();
    for (int p = tid; p < NBOX; p += 512) {
        unsigned kept = (keepw[p >> 5] >> (p & 31)) & 1u;
        int n = g_sidx[cls * NBOX + p];
        g_keep[n * NC + cls] = (unsigned char)kept;
    }
}

// ---------------- 7: masked argmax -> obj_preds ----------------
__global__ void k_argmax(float* __restrict__ out) {
    int n = blockIdx.x * 256 + threadIdx.x;
    if (n >= NBOX) return;
    float best = -1.f;
    int bestc = 0;
    for (int c = 1; c < NCLS; c++) {
        float v = g_keep[n * NC + (c - 1)] ? g_probs[n * NCLS + c] : 0.f;
        if (v > best) { best = v; bestc = c; }
    }
    out[OUT_PREDS + n] = (float)bestc;
}

// ---------------- launch ----------------
extern "C" void kernel_launch(void* const* d_in, const int* in_sizes, int n_in,
                              void* d_out, int out_size) {
    const float*  logits = (const float*)d_in[0];
    const float*  vr     = (const float*)d_in[1];
    const float4* boxes  = (const float4*)d_in[2];
    const float*  W      = (const float*)d_in[3];
    const float*  b      = (const float*)d_in[4];
    float* out = (float*)d_out;

    static cudaStream_t s2 = nullptr;
    static cudaEvent_t  evA = nullptr, evB = nullptr;
    if (!s2) {
        cudaStreamCreateWithFlags(&s2, cudaStreamNonBlocking);
        cudaEventCreateWithFlags(&evA, cudaEventDisableTiming);
        cudaEventCreateWithFlags(&evB, cudaEventDisableTiming);
    }

    const int scan_smem = (TRI + 32) * 4;                // 67840
    const int gemm_smem = 256 * 33 * 4 + 32 * 26 * 8;    // 40448
    cudaFuncSetAttribute(k_scan, cudaFuncAttributeMaxDynamicSharedMemorySize, scan_smem);
    cudaFuncSetAttribute(k_gemm, cudaFuncAttributeMaxDynamicSharedMemorySize, gemm_smem);

    // fork point recorded first: GEMM branch is a graph root (runs from t=0)
    cudaEventRecord(evA, 0);
    cudaStreamWaitEvent(s2, evA, 0);

    k_softmax<<<128, 256>>>(logits, out);                          // launch 1
    k_sort<<<NC, 512>>>(boxes);                                    // launch 2
    k_iou<<<dim3(17, NC), 1024>>>();                               // launch 3
    k_scan<<<NC, 512, scan_smem>>>();                              // launch 4 (profiled)
    k_initrel<<<(MROW * NREL + 255) / 256, 256, 0, s2>>>(b, out);  // launch 5
    k_gemm<<<dim3(16, 16), 256, gemm_smem, s2>>>(vr, W, out);      // launch 6
    k_argmax<<<4, 256>>>(out);                                     // launch 7

    cudaEventRecord(evB, s2);
    cudaStreamWaitEvent(0, evB, 0);
}

// round 9
// speedup vs baseline: 1.4335x; 1.0967x over previous
#include <cuda_runtime.h>
#include <cstdint>
#include <cstddef>

#define NBOX 1024
#define NCLS 151
#define NC   150
#define MROW 4096
#define KDIM 4096
#define NREL 51
#define TH   0.3f

#define OUT_PREDS (NBOX * NCLS)        // 154624
#define OUT_REL   (OUT_PREDS + NBOX)   // 155648
#define NTASK 528                      // triangle (g,w) tiles per class
#define TRI   16928                    // padded triangle words per class

// colbase[w] = 16*w*(w+1) + w  (32*(w+1) rows per word w, +1 pad word for banks)
__device__ __forceinline__ int colbase(int w) { return 16 * w * (w + 1) + w; }

// ---------------- device scratch ----------------
__device__ float         g_probs[NBOX * NCLS];
__device__ float4        g_sboxes[NC * NBOX];
__device__ int           g_sidx[NC * NBOX];
__device__ unsigned      g_masktri[NC * TRI];          // 10.2 MB, triangle-packed
__device__ unsigned char g_keep[NBOX * NC];            // [box][cls]

// ---------------- packed fp32x2 helpers ----------------
__device__ __forceinline__ unsigned long long pack2(float lo, float hi) {
    unsigned long long r;
    asm("mov.b64 %0, {%1, %2};" : "=l"(r) : "f"(lo), "f"(hi));
    return r;
}
__device__ __forceinline__ void fma2(unsigned long long& d, unsigned long long a,
                                     unsigned long long b) {
    asm("fma.rn.f32x2 %0, %1, %2, %0;" : "+l"(d) : "l"(a), "l"(b));
}
__device__ __forceinline__ void unpack2(unsigned long long v, float& lo, float& hi) {
    asm("mov.b64 {%0, %1}, %2;" : "=f"(lo), "=f"(hi) : "l"(v));
}

// ---------------- 1: softmax (warp per row) + logits passthrough ----------------
__global__ void k_softmax(const float* __restrict__ logits, float* __restrict__ out) {
    int warp = threadIdx.x >> 5, lane = threadIdx.x & 31;
    int row = blockIdx.x * 8 + warp;
    const float* rl = logits + row * NCLS;
    float v[5];
    float mx = -3.4e38f;
#pragma unroll
    for (int t = 0; t < 5; t++) {
        int c = lane + 32 * t;
        v[t] = (c < NCLS) ? rl[c] : -3.4e38f;
        mx = fmaxf(mx, v[t]);
    }
#pragma unroll
    for (int o = 16; o > 0; o >>= 1) mx = fmaxf(mx, __shfl_xor_sync(0xffffffffu, mx, o));
    float s = 0.f;
#pragma unroll
    for (int t = 0; t < 5; t++) {
        int c = lane + 32 * t;
        v[t] = (c < NCLS) ? expf(v[t] - mx) : 0.f;
        s += v[t];
    }
#pragma unroll
    for (int o = 16; o > 0; o >>= 1) s += __shfl_xor_sync(0xffffffffu, s, o);
#pragma unroll
    for (int t = 0; t < 5; t++) {
        int c = lane + 32 * t;
        if (c < NCLS) {
            g_probs[row * NCLS + c] = v[t] / s;
            out[row * NCLS + c]     = rl[c];
        }
    }
}

// ---------------- 2: init rel_dists region with bias ----------------
__global__ void k_initrel(const float* __restrict__ b, float* __restrict__ out) {
    int i = blockIdx.x * 256 + threadIdx.x;
    if (i < MROW * NREL) out[OUT_REL + i] = b[i % NREL];
}

// ---------------- 3: GEMM  rel = vr @ W.T + b  (f32x2, M-tile 256, 16-way ksplit)
__global__ __launch_bounds__(256) void k_gemm(const float* __restrict__ vr,
                                              const float* __restrict__ W,
                                              float* __restrict__ out) {
    extern __shared__ float smf[];
    float* As = smf;                                                // [256][33]
    unsigned long long* Wp = (unsigned long long*)(smf + 256 * 33); // [32][26]
    float* Wpf = (float*)Wp;

    int tid = threadIdx.x;
    int mg = tid >> 1, pg = tid & 1, pbase = pg * 13;
    int m0 = blockIdx.x * 256, k0 = blockIdx.y * 256;

    unsigned long long acc[2][13];
#pragma unroll
    for (int r = 0; r < 2; r++)
#pragma unroll
        for (int p = 0; p < 13; p++) acc[r][p] = 0ull;

    for (int kc = 0; kc < 256; kc += 32) {
#pragma unroll
        for (int u = 0; u < 8; u++) {
            int idx = u * 256 + tid;
            int row = idx >> 3, kq = idx & 7;
            float4 v = *(const float4*)&vr[(size_t)(m0 + row) * KDIM + (k0 + kc) + kq * 4];
            float* d = &As[row * 33 + kq * 4];
            d[0] = v.x; d[1] = v.y; d[2] = v.z; d[3] = v.w;
        }
        for (int u = tid; u < 52 * 32; u += 256) {
            int r = u >> 5, kk = u & 31;
            float val = (r < NREL) ? W[r * KDIM + (k0 + kc) + kk] : 0.f;
            Wpf[kk * 52 + r] = val;
        }
        __syncthreads();

        for (int kk = 0; kk < 32; kk++) {
            float a0 = As[(mg * 2 + 0) * 33 + kk];
            float a1 = As[(mg * 2 + 1) * 33 + kk];
            unsigned long long av0 = pack2(a0, a0), av1 = pack2(a1, a1);
#pragma unroll
            for (int p = 0; p < 13; p++) {
                unsigned long long wv = Wp[kk * 26 + pbase + p];
                fma2(acc[0][p], av0, wv);
                fma2(acc[1][p], av1, wv);
            }
        }
        __syncthreads();
    }

#pragma unroll
    for (int r = 0; r < 2; r++) {
        int row = m0 + mg * 2 + r;
#pragma unroll
        for (int p = 0; p < 13; p++) {
            float lo, hi;
            unpack2(acc[r][p], lo, hi);
            int rc = (pbase + p) * 2;
            atomicAdd(&out[OUT_REL + row * NREL + rc], lo);
            if (rc + 1 < NREL) atomicAdd(&out[OUT_REL + row * NREL + rc + 1], hi);
        }
    }
}

// ---------------- 4: per-class descending sort (register/shfl bitonic) -----------
__global__ __launch_bounds__(512) void k_sort(const float4* __restrict__ boxes) {
    __shared__ unsigned long long keys[NBOX];
    int t = threadIdx.x;
    int cls = blockIdx.x + 1;

    auto mkkey = [&](int p) {
        float sc = g_probs[p * NCLS + cls];
        return ((unsigned long long)__float_as_uint(sc) << 32) |
               (unsigned)(0xFFFFFFFFu - (unsigned)p);
    };
    unsigned long long v0 = mkkey(2 * t), v1 = mkkey(2 * t + 1);

    for (int k = 2; k <= NBOX; k <<= 1) {
        for (int j = k >> 1; j >= 1; j >>= 1) {
            if (j >= 64) {
                __syncthreads();
                keys[2 * t] = v0; keys[2 * t + 1] = v1;
                __syncthreads();
                unsigned long long u0 = keys[(2 * t) ^ j];
                unsigned long long u1 = keys[((2 * t) ^ j) + 1];
                bool takeMax = (((t & (j >> 1)) == 0) == ((t & (k >> 1)) == 0));
                v0 = takeMax ? (v0 > u0 ? v0 : u0) : (v0 < u0 ? v0 : u0);
                v1 = takeMax ? (v1 > u1 ? v1 : u1) : (v1 < u1 ? v1 : u1);
            } else if (j >= 2) {
                unsigned long long u0 = __shfl_xor_sync(0xffffffffu, v0, j >> 1);
                unsigned long long u1 = __shfl_xor_sync(0xffffffffu, v1, j >> 1);
                bool takeMax = (((t & (j >> 1)) == 0) == ((t & (k >> 1)) == 0));
                v0 = takeMax ? (v0 > u0 ? v0 : u0) : (v0 < u0 ? v0 : u0);
                v1 = takeMax ? (v1 > u1 ? v1 : u1) : (v1 < u1 ? v1 : u1);
            } else {
                bool desc = ((t & (k >> 1)) == 0);
                unsigned long long hi = v0 > v1 ? v0 : v1;
                unsigned long long lo = v0 > v1 ? v1 : v0;
                v0 = desc ? hi : lo;
                v1 = desc ? lo : hi;
            }
        }
    }
    int n0 = (int)(0xFFFFFFFFu - (unsigned)v0);
    int n1 = (int)(0xFFFFFFFFu - (unsigned)v1);
    g_sidx[(cls - 1) * NBOX + 2 * t]     = n0;
    g_sidx[(cls - 1) * NBOX + 2 * t + 1] = n1;
    g_sboxes[(cls - 1) * NBOX + 2 * t]     = boxes[n0 * NCLS + cls];
    g_sboxes[(cls - 1) * NBOX + 2 * t + 1] = boxes[n1 * NCLS + cls];
}

// ---------------- 5: suppression bitmask -> triangle-packed gmem -----------------
__global__ __launch_bounds__(1024) void k_iou() {
    __shared__ float4 sb[NBOX];
    __shared__ float  ta[NBOX];
    int tid = threadIdx.x, cls = blockIdx.y;
    {
        float4 b4 = g_sboxes[cls * NBOX + tid];
        sb[tid] = b4;
        ta[tid] = TH * ((b4.z - b4.x) * (b4.w - b4.y));
    }
    __syncthreads();
    int task = blockIdx.x * 32 + (tid >> 5);
    if (task >= NTASK) return;

    // invert base(g) = 32g - g(g-1)/2
    int g = (int)((65.0f - sqrtf(4225.0f - 8.0f * (float)task)) * 0.5f);
    while (32 * (g + 1) - (((g + 1) * g) >> 1) <= task) g++;
    while (32 * g - ((g * (g - 1)) >> 1) > task) g--;
    int w = g + (task - (32 * g - ((g * (g - 1)) >> 1)));

    int lane = tid & 31;
    int r = (g << 5) | lane;
    float4 bi = sb[r];
    float c3i = ta[r] + TH * 1e-10f;
    int jbase = w << 5;
    unsigned bits = 0;
#pragma unroll 8
    for (int b = 0; b < 32; b++) {
        float4 bj = sb[jbase + b];                 // broadcast (warp-uniform)
        float rhs = c3i + ta[jbase + b];
        float ix1 = fmaxf(bi.x, bj.x);
        float iy1 = fmaxf(bi.y, bj.y);
        float ix2 = fminf(bi.z, bj.z);
        float iy2 = fminf(bi.w, bj.w);
        float iw = fmaxf(ix2 - ix1, 0.f);
        float ih = fmaxf(iy2 - iy1, 0.f);
        float inter = iw * ih;
        if (fmaf(TH, inter, inter) > rhs) bits |= (1u << b);
    }
    if (w == g) bits &= (0xFFFFFFFEu << lane);     // only j > row in diag word
    g_masktri[cls * TRI + colbase(w) + r] = bits;  // coalesced 128B line
}

// ---------------- 6: greedy scan: reg-resident greedy + DENSE masked OR ----------
__global__ __launch_bounds__(512, 1) void k_scan() {
    extern __shared__ unsigned sm[];   // tri[TRI] + keepw[32]
    unsigned* tri = sm;
    unsigned* keepw = sm + TRI;
    int tid = threadIdx.x, cls = blockIdx.x;
    const uint4* src = (const uint4*)(g_masktri + (size_t)cls * TRI);
    uint4* dst = (uint4*)sm;
    for (int t = tid; t < TRI / 4; t += 512) dst[t] = src[t];
    __syncthreads();

    if (tid < 32) {
        int l = tid;
        int cbl = colbase(l);
        unsigned rem = 0;                          // lane l owns word l
        for (int wb = 0; wb < 32; wb++) {
            int cbw = colbase(wb) + (wb << 5);
            unsigned alive = ~__shfl_sync(0xffffffffu, rem, wb);
            unsigned K = 0;
            // greedy: 3-op/step chain; diag loads chunked (16 regs), pipelined
#define GSTEP(B, D) { unsigned m = (unsigned)(((int)(alive << (31 - (B)))) >> 31); \
                      K |= m & (1u << (B)); alive &= ~((D) & m); }
            {
                unsigned e0 = tri[cbw+0],  e1 = tri[cbw+1],  e2 = tri[cbw+2],  e3 = tri[cbw+3];
                unsigned e4 = tri[cbw+4],  e5 = tri[cbw+5],  e6 = tri[cbw+6],  e7 = tri[cbw+7];
                unsigned e8 = tri[cbw+8],  e9 = tri[cbw+9],  e10= tri[cbw+10], e11= tri[cbw+11];
                unsigned e12= tri[cbw+12], e13= tri[cbw+13], e14= tri[cbw+14], e15= tri[cbw+15];
                GSTEP(0,e0)  GSTEP(1,e1)  GSTEP(2,e2)  GSTEP(3,e3)
                GSTEP(4,e4)  GSTEP(5,e5)  GSTEP(6,e6)  GSTEP(7,e7)
                GSTEP(8,e8)  GSTEP(9,e9)  GSTEP(10,e10) GSTEP(11,e11)
                GSTEP(12,e12) GSTEP(13,e13) GSTEP(14,e14) GSTEP(15,e15)
            }
            {
                unsigned e16= tri[cbw+16], e17= tri[cbw+17], e18= tri[cbw+18], e19= tri[cbw+19];
                unsigned e20= tri[cbw+20], e21= tri[cbw+21], e22= tri[cbw+22], e23= tri[cbw+23];
                unsigned e24= tri[cbw+24], e25= tri[cbw+25], e26= tri[cbw+26], e27= tri[cbw+27];
                unsigned e28= tri[cbw+28], e29= tri[cbw+29], e30= tri[cbw+30], e31= tri[cbw+31];
                GSTEP(16,e16) GSTEP(17,e17) GSTEP(18,e18) GSTEP(19,e19)
                GSTEP(20,e20) GSTEP(21,e21) GSTEP(22,e22) GSTEP(23,e23)
                GSTEP(24,e24) GSTEP(25,e25) GSTEP(26,e26) GSTEP(27,e27)
                GSTEP(28,e28) GSTEP(29,e29) GSTEP(30,e30) GSTEP(31,e31)
            }
#undef GSTEP
            if (l == 0) keepw[wb] = K;             // K lane-uniform

            // DENSE masked OR: 32 independent loads, no serial LDS chain.
            // banks (cbl + R) % 32 = (l + R) % 32 -> conflict-free across lanes.
            unsigned guard = (l >= wb) ? 0xFFFFFFFFu : 0u;
            unsigned mKg = K & ((guard) | 0u);     // guard folds into per-bit mask
            unsigned a0 = 0, a1 = 0, a2 = 0, a3 = 0;
            int base = cbl + (wb << 5);
#pragma unroll
            for (int b = 0; b < 32; b += 4) {
                unsigned m0 = (unsigned)(-(int)((mKg >> (b + 0)) & 1u));
                unsigned m1 = (unsigned)(-(int)((mKg >> (b + 1)) & 1u));
                unsigned m2 = (unsigned)(-(int)((mKg >> (b + 2)) & 1u));
                unsigned m3 = (unsigned)(-(int)((mKg >> (b + 3)) & 1u));
                a0 |= tri[base + b + 0] & m0;
                a1 |= tri[base + b + 1] & m1;
                a2 |= tri[base + b + 2] & m2;
                a3 |= tri[base + b + 3] & m3;
            }
            rem |= (a0 | a1) | (a2 | a3);
        }
    }
    __syncthreads();
    for (int p = tid; p < NBOX; p += 512) {
        unsigned kept = (keepw[p >> 5] >> (p & 31)) & 1u;
        int n = g_sidx[cls * NBOX + p];
        g_keep[n * NC + cls] = (unsigned char)kept;
    }
}

// ---------------- 7: masked argmax -> obj_preds ----------------
__global__ void k_argmax(float* __restrict__ out) {
    int n = blockIdx.x * 256 + threadIdx.x;
    if (n >= NBOX) return;
    float best = -1.f;
    int bestc = 0;
    for (int c = 1; c < NCLS; c++) {
        float v = g_keep[n * NC + (c - 1)] ? g_probs[n * NCLS + c] : 0.f;
        if (v > best) { best = v; bestc = c; }
    }
    out[OUT_PREDS + n] = (float)bestc;
}

// ---------------- launch ----------------
extern "C" void kernel_launch(void* const* d_in, const int* in_sizes, int n_in,
                              void* d_out, int out_size) {
    const float*  logits = (const float*)d_in[0];
    const float*  vr     = (const float*)d_in[1];
    const float4* boxes  = (const float4*)d_in[2];
    const float*  W      = (const float*)d_in[3];
    const float*  b      = (const float*)d_in[4];
    float* out = (float*)d_out;

    static cudaStream_t s2 = nullptr;
    static cudaEvent_t  evA = nullptr, evB = nullptr;
    if (!s2) {
        cudaStreamCreateWithFlags(&s2, cudaStreamNonBlocking);
        cudaEventCreateWithFlags(&evA, cudaEventDisableTiming);
        cudaEventCreateWithFlags(&evB, cudaEventDisableTiming);
    }

    const int scan_smem = (TRI + 32) * 4;                // 67840
    const int gemm_smem = 256 * 33 * 4 + 32 * 26 * 8;    // 40448
    cudaFuncSetAttribute(k_scan, cudaFuncAttributeMaxDynamicSharedMemorySize, scan_smem);
    cudaFuncSetAttribute(k_gemm, cudaFuncAttributeMaxDynamicSharedMemorySize, gemm_smem);

    // fork point recorded first: GEMM branch is a graph root (runs from t=0)
    cudaEventRecord(evA, 0);
    cudaStreamWaitEvent(s2, evA, 0);

    k_softmax<<<128, 256>>>(logits, out);                          // launch 1
    k_sort<<<NC, 512>>>(boxes);                                    // launch 2
    k_iou<<<dim3(17, NC), 1024>>>();                               // launch 3
    k_scan<<<NC, 512, scan_smem>>>();                              // launch 4 (profiled)
    k_initrel<<<(MROW * NREL + 255) / 256, 256, 0, s2>>>(b, out);  // launch 5
    k_gemm<<<dim3(16, 16), 256, gemm_smem, s2>>>(vr, W, out);      // launch 6
    k_argmax<<<4, 256>>>(out);                                     // launch 7

    cudaEventRecord(evB, s2);
    cudaStreamWaitEvent(0, evB, 0);
}

// round 11
// speedup vs baseline: 1.6025x; 1.1179x over previous
#include <cuda_runtime.h>
#include <cstdint>
#include <cstddef>

#define NBOX 1024
#define NCLS 151
#define NC   150
#define MROW 4096
#define KDIM 4096
#define NREL 51
#define TH   0.3f

#define OUT_PREDS (NBOX * NCLS)        // 154624
#define OUT_REL   (OUT_PREDS + NBOX)   // 155648
#define NTASK 528                      // triangle (g,w) tiles per class
#define TRI   16928                    // padded triangle words per class

// colbase[w] = 16*w*(w+1) + w  (32*(w+1) rows per word w, +1 pad word for banks)
__device__ __forceinline__ int colbase(int w) { return 16 * w * (w + 1) + w; }

// ---------------- device scratch ----------------
__device__ float         g_probs[NBOX * NCLS];
__device__ float4        g_sboxes[NC * NBOX];
__device__ int           g_sidx[NC * NBOX];
__device__ unsigned      g_masktri[NC * TRI];          // 10.2 MB, triangle-packed
__device__ unsigned char g_keep[NBOX * NC];            // [box][cls]

// ---------------- packed fp32x2 helpers (add/mul/fma/sub ONLY exist) -------------
__device__ __forceinline__ unsigned long long pack2(float lo, float hi) {
    unsigned long long r;
    asm("mov.b64 %0, {%1, %2};" : "=l"(r) : "f"(lo), "f"(hi));
    return r;
}
__device__ __forceinline__ void fma2(unsigned long long& d, unsigned long long a,
                                     unsigned long long b) {
    asm("fma.rn.f32x2 %0, %1, %2, %0;" : "+l"(d) : "l"(a), "l"(b));
}
__device__ __forceinline__ void unpack2(unsigned long long v, float& lo, float& hi) {
    asm("mov.b64 {%0, %1}, %2;" : "=f"(lo), "=f"(hi) : "l"(v));
}

// ---------------- 1: softmax (warp per row) + logits passthrough ----------------
__global__ void k_softmax(const float* __restrict__ logits, float* __restrict__ out) {
    int warp = threadIdx.x >> 5, lane = threadIdx.x & 31;
    int row = blockIdx.x * 8 + warp;
    const float* rl = logits + row * NCLS;
    float v[5];
    float mx = -3.4e38f;
#pragma unroll
    for (int t = 0; t < 5; t++) {
        int c = lane + 32 * t;
        v[t] = (c < NCLS) ? rl[c] : -3.4e38f;
        mx = fmaxf(mx, v[t]);
    }
#pragma unroll
    for (int o = 16; o > 0; o >>= 1) mx = fmaxf(mx, __shfl_xor_sync(0xffffffffu, mx, o));
    float s = 0.f;
#pragma unroll
    for (int t = 0; t < 5; t++) {
        int c = lane + 32 * t;
        v[t] = (c < NCLS) ? expf(v[t] - mx) : 0.f;
        s += v[t];
    }
#pragma unroll
    for (int o = 16; o > 0; o >>= 1) s += __shfl_xor_sync(0xffffffffu, s, o);
#pragma unroll
    for (int t = 0; t < 5; t++) {
        int c = lane + 32 * t;
        if (c < NCLS) {
            g_probs[row * NCLS + c] = v[t] / s;
            out[row * NCLS + c]     = rl[c];
        }
    }
}

// ---------------- 2: init rel_dists region with bias ----------------
__global__ void k_initrel(const float* __restrict__ b, float* __restrict__ out) {
    int i = blockIdx.x * 256 + threadIdx.x;
    if (i < MROW * NREL) out[OUT_REL + i] = b[i % NREL];
}

// ---------------- 3: GEMM  rel = vr @ W.T + b  (f32x2, M-tile 256, 16-way ksplit)
__global__ __launch_bounds__(256) void k_gemm(const float* __restrict__ vr,
                                              const float* __restrict__ W,
                                              float* __restrict__ out) {
    extern __shared__ float smf[];
    float* As = smf;                                                // [256][33]
    unsigned long long* Wp = (unsigned long long*)(smf + 256 * 33); // [32][26]
    float* Wpf = (float*)Wp;

    int tid = threadIdx.x;
    int mg = tid >> 1, pg = tid & 1, pbase = pg * 13;
    int m0 = blockIdx.x * 256, k0 = blockIdx.y * 256;

    unsigned long long acc[2][13];
#pragma unroll
    for (int r = 0; r < 2; r++)
#pragma unroll
        for (int p = 0; p < 13; p++) acc[r][p] = 0ull;

    for (int kc = 0; kc < 256; kc += 32) {
#pragma unroll
        for (int u = 0; u < 8; u++) {
            int idx = u * 256 + tid;
            int row = idx >> 3, kq = idx & 7;
            float4 v = *(const float4*)&vr[(size_t)(m0 + row) * KDIM + (k0 + kc) + kq * 4];
            float* d = &As[row * 33 + kq * 4];
            d[0] = v.x; d[1] = v.y; d[2] = v.z; d[3] = v.w;
        }
        for (int u = tid; u < 52 * 32; u += 256) {
            int r = u >> 5, kk = u & 31;
            float val = (r < NREL) ? W[r * KDIM + (k0 + kc) + kk] : 0.f;
            Wpf[kk * 52 + r] = val;
        }
        __syncthreads();

        for (int kk = 0; kk < 32; kk++) {
            float a0 = As[(mg * 2 + 0) * 33 + kk];
            float a1 = As[(mg * 2 + 1) * 33 + kk];
            unsigned long long av0 = pack2(a0, a0), av1 = pack2(a1, a1);
#pragma unroll
            for (int p = 0; p < 13; p++) {
                unsigned long long wv = Wp[kk * 26 + pbase + p];
                fma2(acc[0][p], av0, wv);
                fma2(acc[1][p], av1, wv);
            }
        }
        __syncthreads();
    }

#pragma unroll
    for (int r = 0; r < 2; r++) {
        int row = m0 + mg * 2 + r;
#pragma unroll
        for (int p = 0; p < 13; p++) {
            float lo, hi;
            unpack2(acc[r][p], lo, hi);
            int rc = (pbase + p) * 2;
            atomicAdd(&out[OUT_REL + row * NREL + rc], lo);
            if (rc + 1 < NREL) atomicAdd(&out[OUT_REL + row * NREL + rc + 1], hi);
        }
    }
}

// ---------------- 4: per-class descending sort (register/shfl bitonic) -----------
__global__ __launch_bounds__(512) void k_sort(const float4* __restrict__ boxes) {
    __shared__ unsigned long long keys[NBOX];
    int t = threadIdx.x;
    int cls = blockIdx.x + 1;

    auto mkkey = [&](int p) {
        float sc = g_probs[p * NCLS + cls];
        return ((unsigned long long)__float_as_uint(sc) << 32) |
               (unsigned)(0xFFFFFFFFu - (unsigned)p);
    };
    unsigned long long v0 = mkkey(2 * t), v1 = mkkey(2 * t + 1);

    for (int k = 2; k <= NBOX; k <<= 1) {
        for (int j = k >> 1; j >= 1; j >>= 1) {
            if (j >= 64) {
                __syncthreads();
                keys[2 * t] = v0; keys[2 * t + 1] = v1;
                __syncthreads();
                unsigned long long u0 = keys[(2 * t) ^ j];
                unsigned long long u1 = keys[((2 * t) ^ j) + 1];
                bool takeMax = (((t & (j >> 1)) == 0) == ((t & (k >> 1)) == 0));
                v0 = takeMax ? (v0 > u0 ? v0 : u0) : (v0 < u0 ? v0 : u0);
                v1 = takeMax ? (v1 > u1 ? v1 : u1) : (v1 < u1 ? v1 : u1);
            } else if (j >= 2) {
                unsigned long long u0 = __shfl_xor_sync(0xffffffffu, v0, j >> 1);
                unsigned long long u1 = __shfl_xor_sync(0xffffffffu, v1, j >> 1);
                bool takeMax = (((t & (j >> 1)) == 0) == ((t & (k >> 1)) == 0));
                v0 = takeMax ? (v0 > u0 ? v0 : u0) : (v0 < u0 ? v0 : u0);
                v1 = takeMax ? (v1 > u1 ? v1 : u1) : (v1 < u1 ? v1 : u1);
            } else {
                bool desc = ((t & (k >> 1)) == 0);
                unsigned long long hi = v0 > v1 ? v0 : v1;
                unsigned long long lo = v0 > v1 ? v1 : v0;
                v0 = desc ? hi : lo;
                v1 = desc ? lo : hi;
            }
        }
    }
    int n0 = (int)(0xFFFFFFFFu - (unsigned)v0);
    int n1 = (int)(0xFFFFFFFFu - (unsigned)v1);
    g_sidx[(cls - 1) * NBOX + 2 * t]     = n0;
    g_sidx[(cls - 1) * NBOX + 2 * t + 1] = n1;
    g_sboxes[(cls - 1) * NBOX + 2 * t]     = boxes[n0 * NCLS + cls];
    g_sboxes[(cls - 1) * NBOX + 2 * t + 1] = boxes[n1 * NCLS + cls];
}

// ---------------- 5: suppression bitmask (proven scalar) -> triangle gmem --------
__global__ __launch_bounds__(1024) void k_iou() {
    __shared__ float4 sb[NBOX];
    __shared__ float  ta[NBOX];
    int tid = threadIdx.x, cls = blockIdx.y;
    {
        float4 b4 = g_sboxes[cls * NBOX + tid];
        sb[tid] = b4;
        ta[tid] = TH * ((b4.z - b4.x) * (b4.w - b4.y));
    }
    __syncthreads();
    int task = blockIdx.x * 32 + (tid >> 5);
    if (task >= NTASK) return;

    // invert base(g) = 32g - g(g-1)/2
    int g = (int)((65.0f - sqrtf(4225.0f - 8.0f * (float)task)) * 0.5f);
    while (32 * (g + 1) - (((g + 1) * g) >> 1) <= task) g++;
    while (32 * g - ((g * (g - 1)) >> 1) > task) g--;
    int w = g + (task - (32 * g - ((g * (g - 1)) >> 1)));

    int lane = tid & 31;
    int r = (g << 5) | lane;
    float4 bi = sb[r];
    float c3i = ta[r] + TH * 1e-10f;
    int jbase = w << 5;
    unsigned bits = 0;
#pragma unroll 8
    for (int b = 0; b < 32; b++) {
        float4 bj = sb[jbase + b];                 // broadcast (warp-uniform)
        float rhs = c3i + ta[jbase + b];
        float ix1 = fmaxf(bi.x, bj.x);
        float iy1 = fmaxf(bi.y, bj.y);
        float ix2 = fminf(bi.z, bj.z);
        float iy2 = fminf(bi.w, bj.w);
        float iw = fmaxf(ix2 - ix1, 0.f);
        float ih = fmaxf(iy2 - iy1, 0.f);
        float inter = iw * ih;
        if (fmaf(TH, inter, inter) > rhs) bits |= (1u << b);
    }
    if (w == g) bits &= (0xFFFFFFFEu << lane);     // only j > row in diag word
    g_masktri[cls * TRI + colbase(w) + r] = bits;  // coalesced 128B line
}

// ---------------- 6: greedy scan: reg-resident greedy + DENSE masked OR ----------
__global__ __launch_bounds__(512, 1) void k_scan() {
    extern __shared__ unsigned sm[];   // tri[TRI] + keepw[32]
    unsigned* tri = sm;
    unsigned* keepw = sm + TRI;
    int tid = threadIdx.x, cls = blockIdx.x;
    const uint4* src = (const uint4*)(g_masktri + (size_t)cls * TRI);
    uint4* dst = (uint4*)sm;
    for (int t = tid; t < TRI / 4; t += 512) dst[t] = src[t];
    __syncthreads();

    if (tid < 32) {
        int l = tid;
        int cbl = colbase(l);
        unsigned rem = 0;                          // lane l owns word l
        for (int wb = 0; wb < 32; wb++) {
            int cbw = colbase(wb) + (wb << 5);
            unsigned alive = ~__shfl_sync(0xffffffffu, rem, wb);
            unsigned K = 0;
#define GSTEP(B, D) { unsigned m = (unsigned)(((int)(alive << (31 - (B)))) >> 31); \
                      K |= m & (1u << (B)); alive &= ~((D) & m); }
            {
                unsigned e0 = tri[cbw+0],  e1 = tri[cbw+1],  e2 = tri[cbw+2],  e3 = tri[cbw+3];
                unsigned e4 = tri[cbw+4],  e5 = tri[cbw+5],  e6 = tri[cbw+6],  e7 = tri[cbw+7];
                unsigned e8 = tri[cbw+8],  e9 = tri[cbw+9],  e10= tri[cbw+10], e11= tri[cbw+11];
                unsigned e12= tri[cbw+12], e13= tri[cbw+13], e14= tri[cbw+14], e15= tri[cbw+15];
                GSTEP(0,e0)  GSTEP(1,e1)  GSTEP(2,e2)  GSTEP(3,e3)
                GSTEP(4,e4)  GSTEP(5,e5)  GSTEP(6,e6)  GSTEP(7,e7)
                GSTEP(8,e8)  GSTEP(9,e9)  GSTEP(10,e10) GSTEP(11,e11)
                GSTEP(12,e12) GSTEP(13,e13) GSTEP(14,e14) GSTEP(15,e15)
            }
            {
                unsigned e16= tri[cbw+16], e17= tri[cbw+17], e18= tri[cbw+18], e19= tri[cbw+19];
                unsigned e20= tri[cbw+20], e21= tri[cbw+21], e22= tri[cbw+22], e23= tri[cbw+23];
                unsigned e24= tri[cbw+24], e25= tri[cbw+25], e26= tri[cbw+26], e27= tri[cbw+27];
                unsigned e28= tri[cbw+28], e29= tri[cbw+29], e30= tri[cbw+30], e31= tri[cbw+31];
                GSTEP(16,e16) GSTEP(17,e17) GSTEP(18,e18) GSTEP(19,e19)
                GSTEP(20,e20) GSTEP(21,e21) GSTEP(22,e22) GSTEP(23,e23)
                GSTEP(24,e24) GSTEP(25,e25) GSTEP(26,e26) GSTEP(27,e27)
                GSTEP(28,e28) GSTEP(29,e29) GSTEP(30,e30) GSTEP(31,e31)
            }
#undef GSTEP
            if (l == 0) keepw[wb] = K;             // K lane-uniform

            unsigned guard = (l >= wb) ? 0xFFFFFFFFu : 0u;
            unsigned mKg = K & guard;
            unsigned a0 = 0, a1 = 0, a2 = 0, a3 = 0;
            int base = cbl + (wb << 5);
#pragma unroll
            for (int b = 0; b < 32; b += 4) {
                unsigned m0 = (unsigned)(-(int)((mKg >> (b + 0)) & 1u));
                unsigned m1 = (unsigned)(-(int)((mKg >> (b + 1)) & 1u));
                unsigned m2 = (unsigned)(-(int)((mKg >> (b + 2)) & 1u));
                unsigned m3 = (unsigned)(-(int)((mKg >> (b + 3)) & 1u));
                a0 |= tri[base + b + 0] & m0;
                a1 |= tri[base + b + 1] & m1;
                a2 |= tri[base + b + 2] & m2;
                a3 |= tri[base + b + 3] & m3;
            }
            rem |= (a0 | a1) | (a2 | a3);
        }
    }
    __syncthreads();
    for (int p = tid; p < NBOX; p += 512) {
        unsigned kept = (keepw[p >> 5] >> (p & 31)) & 1u;
        int n = g_sidx[cls * NBOX + p];
        g_keep[n * NC + cls] = (unsigned char)kept;
    }
}

// ---------------- 7: masked argmax -> obj_preds ----------------
__global__ void k_argmax(float* __restrict__ out) {
    int n = blockIdx.x * 256 + threadIdx.x;
    if (n >= NBOX) return;
    float best = -1.f;
    int bestc = 0;
    for (int c = 1; c < NCLS; c++) {
        float v = g_keep[n * NC + (c - 1)] ? g_probs[n * NCLS + c] : 0.f;
        if (v > best) { best = v; bestc = c; }
    }
    out[OUT_PREDS + n] = (float)bestc;
}

// ---------------- launch: GEMM branch packed into k_scan's idle window -----------
extern "C" void kernel_launch(void* const* d_in, const int* in_sizes, int n_in,
                              void* d_out, int out_size) {
    const float*  logits = (const float*)d_in[0];
    const float*  vr     = (const float*)d_in[1];
    const float4* boxes  = (const float4*)d_in[2];
    const float*  W      = (const float*)d_in[3];
    const float*  b      = (const float*)d_in[4];
    float* out = (float*)d_out;

    static cudaStream_t s2 = nullptr;
    static cudaEvent_t  evI = nullptr, evB = nullptr;
    if (!s2) {
        cudaStreamCreateWithFlags(&s2, cudaStreamNonBlocking);
        cudaEventCreateWithFlags(&evI, cudaEventDisableTiming);
        cudaEventCreateWithFlags(&evB, cudaEventDisableTiming);
    }

    const int scan_smem = (TRI + 32) * 4;                // 67840
    const int gemm_smem = 256 * 33 * 4 + 32 * 26 * 8;    // 40448
    cudaFuncSetAttribute(k_scan, cudaFuncAttributeMaxDynamicSharedMemorySize, scan_smem);
    cudaFuncSetAttribute(k_gemm, cudaFuncAttributeMaxDynamicSharedMemorySize, gemm_smem);

    // NMS chain front (issue-saturated; GEMM would only steal slots here)
    k_softmax<<<128, 256>>>(logits, out);                          // launch 1
    k_sort<<<NC, 512>>>(boxes);                                    // launch 2
    k_iou<<<dim3(17, NC), 1024>>>();                               // launch 3
    cudaEventRecord(evI, 0);                                       // after iou

    k_scan<<<NC, 512, scan_smem>>>();                              // launch 4 (profiled)

    // GEMM branch rides k_scan's ~90%-idle window
    cudaStreamWaitEvent(s2, evI, 0);
    k_initrel<<<(MROW * NREL + 255) / 256, 256, 0, s2>>>(b, out);  // launch 5
    k_gemm<<<dim3(16, 16), 256, gemm_smem, s2>>>(vr, W, out);      // launch 6

    k_argmax<<<4, 256>>>(out);                                     // launch 7

    cudaEventRecord(evB, s2);
    cudaStreamWaitEvent(0, evB, 0);
}